// round 8
// baseline (speedup 1.0000x reference)
#include <cuda_runtime.h>
#include <cuda_bf16.h>
#include <cstdint>

#define IMGS   128
#define EMB    256
#define NPIX   32768
#define VOCAB  4096
#define NLRING 12          // per-(lane,row) ring capacity
#define NC_MAX 48          // max candidates per pixel (4 lanes x 12)

__device__ float g_csq[VOCAB];
__device__ float g_csqh[VOCAB];
__device__ int   g_tok[NPIX];
__device__ __nv_bfloat16 g_cbh[VOCAB * EMB];
__device__ unsigned short g_cand[NPIX][NC_MAX];
__device__ int   g_cnt[NPIX];
__device__ int   g_nfb;
__device__ int   g_fblist[NPIX];

__device__ __forceinline__ unsigned int f2ord(float f) {
    unsigned int u = __float_as_uint(f);
    return (u & 0x80000000u) ? ~u : (u | 0x80000000u);
}
__device__ __forceinline__ uint32_t smem_u32(const void* p) {
    uint32_t a;
    asm("{ .reg .u64 t; cvta.to.shared.u64 t, %1; cvt.u32.u64 %0, t; }" : "=r"(a) : "l"(p));
    return a;
}

#define LDM4(r0, r1, r2, r3, addr)                                              \
    asm volatile("ldmatrix.sync.aligned.m8n8.x4.shared.b16 {%0,%1,%2,%3}, [%4];"\
        : "=r"(r0), "=r"(r1), "=r"(r2), "=r"(r3) : "r"(addr))

#define MMA16816(d, a0, a1, a2, a3, b0, b1)                                     \
    asm volatile("mma.sync.aligned.m16n8k16.row.col.f32.bf16.bf16.f32 "         \
        "{%0,%1,%2,%3},{%4,%5,%6,%7},{%8,%9},{%0,%1,%2,%3};"                    \
        : "+f"((d)[0]), "+f"((d)[1]), "+f"((d)[2]), "+f"((d)[3])                \
        : "r"(a0), "r"(a1), "r"(a2), "r"(a3), "r"(b0), "r"(b1))

#define CPA16(dst, src)                                                         \
    asm volatile("cp.async.cg.shared.global [%0], [%1], 16;" :: "r"(dst), "l"(src))
#define CP_COMMIT() asm volatile("cp.async.commit_group;" ::: "memory")

// ---------------------------------------------------------------------------
__global__ void __launch_bounds__(256) k_prep(const float* __restrict__ cb) {
    __shared__ float red[8];
    const int r = blockIdx.x, t = threadIdx.x;
    if (r == 0 && t == 0) g_nfb = 0;
    float v = cb[r * 256 + t];
    g_cbh[r * 256 + t] = __float2bfloat16(v);
    float s = v * v;
    #pragma unroll
    for (int o = 16; o; o >>= 1) s += __shfl_down_sync(0xFFFFFFFFu, s, o);
    if ((t & 31) == 0) red[t >> 5] = s;
    __syncthreads();
    if (t == 0) {
        float tot = 0.f;
        #pragma unroll
        for (int i = 0; i < 8; i++) tot += red[i];
        g_csq[r] = tot; g_csqh[r] = 0.5f * tot;
    }
}

// ---------------------------------------------------------------------------
// fp32 256x256x256 GEMM (pre/post)
// ---------------------------------------------------------------------------
template<bool XFORM>
__global__ void __launch_bounds__(256) k_gemm256(
    const float* __restrict__ W, const float* __restrict__ bias,
    const float* __restrict__ In, float* __restrict__ Out)
{
    __shared__ float Ws[16][68];
    __shared__ float Bs[16][64];
    const int img = blockIdx.z;
    const int m0 = blockIdx.y * 64, n0 = blockIdx.x * 64;
    const float* in = In + (size_t)img * 65536;
    float* out = Out + (size_t)img * 65536;
    const int t = threadIdx.x;
    const int ty = t >> 4, tx = t & 15;
    float acc[4][4] = {};
    for (int k0 = 0; k0 < 256; k0 += 16) {
        {
            int row = t >> 2, c4 = (t & 3) * 4;
            float4 w4 = *reinterpret_cast<const float4*>(&W[(m0 + row) * 256 + k0 + c4]);
            Ws[c4 + 0][row] = w4.x; Ws[c4 + 1][row] = w4.y;
            Ws[c4 + 2][row] = w4.z; Ws[c4 + 3][row] = w4.w;
        }
        {
            int kk = t >> 4, n4 = (t & 15) * 4;
            float4 b4 = *reinterpret_cast<const float4*>(&in[(k0 + kk) * 256 + n0 + n4]);
            if (XFORM) {
                b4.x = 2.f * b4.x - 1.f; b4.y = 2.f * b4.y - 1.f;
                b4.z = 2.f * b4.z - 1.f; b4.w = 2.f * b4.w - 1.f;
            }
            *reinterpret_cast<float4*>(&Bs[kk][n4]) = b4;
        }
        __syncthreads();
        #pragma unroll
        for (int kk = 0; kk < 16; kk++) {
            float a[4], b[4];
            *reinterpret_cast<float4*>(a) = *reinterpret_cast<float4*>(&Ws[kk][ty * 4]);
            *reinterpret_cast<float4*>(b) = *reinterpret_cast<float4*>(&Bs[kk][tx * 4]);
            #pragma unroll
            for (int i = 0; i < 4; i++)
                #pragma unroll
                for (int j = 0; j < 4; j++)
                    acc[i][j] += a[i] * b[j];
        }
        __syncthreads();
    }
    #pragma unroll
    for (int i = 0; i < 4; i++) {
        int m = m0 + ty * 4 + i;
        float bm = bias[m];
        float4 o;
        o.x = acc[i][0] + bm; o.y = acc[i][1] + bm;
        o.z = acc[i][2] + bm; o.w = acc[i][3] + bm;
        *reinterpret_cast<float4*>(&out[m * 256 + n0 + tx * 4]) = o;
    }
}

// ---------------------------------------------------------------------------
// bf16 mma.sync score GEMM, register-local prune into per-lane smem rings.
// SMEM: A 64KB | B0 16KB | B1 16KB | csq 256B | rings 12KB
// ---------------------------------------------------------------------------
#define AOFF      0
#define B0OFF     65536
#define B1OFF     81920
#define CSQOFF    98304
#define RINGOFF   98560
#define SMEM_DIST 110848
#define MARGIN    2.5e-5f

__global__ void __launch_bounds__(256, 2) k_dist_mma(const float* __restrict__ z) {
    extern __shared__ char smem[];
    const uint32_t sb = smem_u32(smem);
    const int t = threadIdx.x;
    const int wid = t >> 5, lane = t & 31;
    const int n_base = blockIdx.x * 128;

    // ---- A build: z (fp32 [e][pix]) -> bf16 swizzled [pix][e] (scratch = B0) ----
    {
        const float* zsrc = z + (size_t)(n_base >> 8) * 65536 + (n_base & 255);
        float* scr = reinterpret_cast<float*>(smem + B0OFF);   // 32e x 128pix fp32
        for (int kb = 0; kb < 8; kb++) {
            int e_l = t >> 3;
            int pg = (t & 7) * 16;
            const float4* s4 = reinterpret_cast<const float4*>(zsrc + (kb * 32 + e_l) * 256 + pg);
            float4 v0 = s4[0], v1 = s4[1], v2 = s4[2], v3 = s4[3];
            float4* d4 = reinterpret_cast<float4*>(scr + e_l * 128 + pg);
            d4[0] = v0; d4[1] = v1; d4[2] = v2; d4[3] = v3;
            __syncthreads();
            int pix = t & 127, half = t >> 7;
            #pragma unroll
            for (int jj = 0; jj < 8; jj++) {
                int el0 = (half * 8 + jj) * 2;
                float a = scr[el0 * 128 + pix], b = scr[(el0 + 1) * 128 + pix];
                uint32_t u;
                asm("cvt.rn.bf16x2.f32 %0, %1, %2;" : "=r"(u) : "f"(b), "f"(a));
                int eg = kb * 32 + el0;
                uint32_t unit = (uint32_t)(eg >> 3);
                uint32_t su = (unit & 24) | ((unit ^ (uint32_t)(pix & 7)) & 7);
                uint32_t addr = sb + AOFF + (uint32_t)pix * 512 + su * 16 + (eg & 7) * 2;
                asm volatile("st.shared.b32 [%0], %1;" :: "r"(addr), "r"(u) : "memory");
            }
            __syncthreads();
        }
    }

    const int wbase = wid * 16;
    const int arow = wbase + (lane & 7) + ((lane >> 3) & 1) * 8;
    const uint32_t aswz = (uint32_t)(arow & 7);
    const uint32_t abase = sb + AOFF + (uint32_t)arow * 512;
    const int ag2 = lane >> 4;
    const int brp = ((lane >> 4) & 1) * 8 + (lane & 7);
    const int bg1 = (lane >> 3) & 1;
    float* csq_s = reinterpret_cast<float*>(smem + CSQOFF);
    unsigned short* ringp =
        reinterpret_cast<unsigned short*>(smem + RINGOFF) + (wid * 32 + lane) * 24;

    float acc[8][4];
    #pragma unroll
    for (int i = 0; i < 8; i++)
        #pragma unroll
        for (int j = 0; j < 4; j++) acc[i][j] = 0.f;

    float rmx_lo = -1e30f, rmx_hi = -1e30f;
    int cl = 0, ch = 0;

    auto loadB = [&](int nt, int kc, uint32_t boff) {
        int code = t >> 2;
        const char* src = reinterpret_cast<const char*>(
            g_cbh + ((size_t)(nt * 64 + code)) * 256 + kc * 128 + (t & 3) * 32);
        uint32_t drow = sb + boff + (uint32_t)code * 256;
        uint32_t sw = (uint32_t)(code & 7);
        #pragma unroll
        for (int i = 0; i < 4; i++) {
            uint32_t u = (uint32_t)((t & 3) * 4 + i);
            uint32_t su = ((u ^ sw) & 7) | (u & 8);
            CPA16(drow + su * 16, src + i * 16);
        }
    };

    loadB(0, 0, B0OFF);
    CP_COMMIT();

    for (int c = 0; c < 128; ++c) {
        const int nt = c >> 1, kc = c & 1;
        if (c < 127) { loadB((c + 1) >> 1, (c + 1) & 1, ((c + 1) & 1) ? B1OFF : B0OFF); CP_COMMIT(); }
        if (kc == 0 && t < 64) csq_s[t] = g_csqh[nt * 64 + t];
        if (c < 127) asm volatile("cp.async.wait_group 1;" ::: "memory");
        else         asm volatile("cp.async.wait_group 0;" ::: "memory");
        __syncthreads();

        const uint32_t bbuf = sb + ((c & 1) ? B1OFF : B0OFF);
        #pragma unroll
        for (int ks = 0; ks < 8; ks++) {
            uint32_t a0, a1, a2, a3;
            {
                uint32_t unit = (uint32_t)(kc * 16 + 2 * ks + ag2);
                uint32_t su = (unit & 24) | ((unit ^ aswz) & 7);
                LDM4(a0, a1, a2, a3, abase + su * 16);
            }
            #pragma unroll
            for (int p = 0; p < 4; p++) {
                int brow = p * 16 + brp;
                uint32_t unit = (uint32_t)(2 * ks + bg1);
                uint32_t su = (unit & 8) | ((unit ^ (uint32_t)(brow & 7)) & 7);
                uint32_t b0, b1, b2, b3;
                LDM4(b0, b1, b2, b3, bbuf + (uint32_t)brow * 256 + su * 16);
                MMA16816(acc[2 * p],     a0, a1, a2, a3, b0, b1);
                MMA16816(acc[2 * p + 1], a0, a1, a2, a3, b2, b3);
            }
        }

        if (kc == 1) {
            const int vtile = nt * 64;
            #pragma unroll
            for (int q = 0; q < 4; ++q) {
                const int cbase = q * 16 + 2 * (lane & 3);
                float2 cq0 = *reinterpret_cast<const float2*>(csq_s + cbase);
                float2 cq1 = *reinterpret_cast<const float2*>(csq_s + cbase + 8);
                const int nf0 = 2 * q, nf1 = 2 * q + 1;
                float s;
                s = acc[nf0][0] - cq0.x;
                if (s > rmx_lo - MARGIN) { if (cl < NLRING) ringp[cl] = (unsigned short)(vtile + cbase);     cl++; rmx_lo = fmaxf(rmx_lo, s); }
                s = acc[nf0][1] - cq0.y;
                if (s > rmx_lo - MARGIN) { if (cl < NLRING) ringp[cl] = (unsigned short)(vtile + cbase + 1); cl++; rmx_lo = fmaxf(rmx_lo, s); }
                s = acc[nf1][0] - cq1.x;
                if (s > rmx_lo - MARGIN) { if (cl < NLRING) ringp[cl] = (unsigned short)(vtile + cbase + 8); cl++; rmx_lo = fmaxf(rmx_lo, s); }
                s = acc[nf1][1] - cq1.y;
                if (s > rmx_lo - MARGIN) { if (cl < NLRING) ringp[cl] = (unsigned short)(vtile + cbase + 9); cl++; rmx_lo = fmaxf(rmx_lo, s); }
                s = acc[nf0][2] - cq0.x;
                if (s > rmx_hi - MARGIN) { if (ch < NLRING) ringp[12 + ch] = (unsigned short)(vtile + cbase);     ch++; rmx_hi = fmaxf(rmx_hi, s); }
                s = acc[nf0][3] - cq0.y;
                if (s > rmx_hi - MARGIN) { if (ch < NLRING) ringp[12 + ch] = (unsigned short)(vtile + cbase + 1); ch++; rmx_hi = fmaxf(rmx_hi, s); }
                s = acc[nf1][2] - cq1.x;
                if (s > rmx_hi - MARGIN) { if (ch < NLRING) ringp[12 + ch] = (unsigned short)(vtile + cbase + 8); ch++; rmx_hi = fmaxf(rmx_hi, s); }
                s = acc[nf1][3] - cq1.y;
                if (s > rmx_hi - MARGIN) { if (ch < NLRING) ringp[12 + ch] = (unsigned short)(vtile + cbase + 9); ch++; rmx_hi = fmaxf(rmx_hi, s); }
                rmx_lo = fmaxf(rmx_lo, __shfl_xor_sync(0xFFFFFFFFu, rmx_lo, 1));
                rmx_lo = fmaxf(rmx_lo, __shfl_xor_sync(0xFFFFFFFFu, rmx_lo, 2));
                rmx_hi = fmaxf(rmx_hi, __shfl_xor_sync(0xFFFFFFFFu, rmx_hi, 1));
                rmx_hi = fmaxf(rmx_hi, __shfl_xor_sync(0xFFFFFFFFu, rmx_hi, 2));
            }
            #pragma unroll
            for (int i = 0; i < 8; i++)
                #pragma unroll
                for (int j = 0; j < 4; j++) acc[i][j] = 0.f;
        }
        __syncthreads();
    }

    const unsigned qb = lane & ~3u;
    const int liq = lane & 3;
    #pragma unroll
    for (int rowsel = 0; rowsel < 2; ++rowsel) {
        int mycnt = rowsel ? ch : cl;
        int l0 = __shfl_sync(0xFFFFFFFFu, mycnt, qb + 0);
        int l1 = __shfl_sync(0xFFFFFFFFu, mycnt, qb + 1);
        int l2 = __shfl_sync(0xFFFFFFFFu, mycnt, qb + 2);
        int l3 = __shfl_sync(0xFFFFFFFFu, mycnt, qb + 3);
        int m0 = min(l0, NLRING), m1 = min(l1, NLRING),
            m2 = min(l2, NLRING), m3 = min(l3, NLRING);
        int tot = m0 + m1 + m2 + m3;
        bool ovf = (l0 > NLRING) | (l1 > NLRING) | (l2 > NLRING) | (l3 > NLRING);
        int pre = (liq > 0 ? m0 : 0) + (liq > 1 ? m1 : 0) + (liq > 2 ? m2 : 0);
        int pix = n_base + wbase + (lane >> 2) + rowsel * 8;
        if (liq == 0) g_cnt[pix] = ovf ? 1000 : tot;
        int myc = min(mycnt, NLRING);
        const unsigned short* rp = ringp + rowsel * 12;
        for (int i = 0; i < myc; ++i) g_cand[pix][pre + i] = rp[i];
    }
}

// ---------------------------------------------------------------------------
// Rescore v2: thread-per-candidate. Block = 32 pixels.
// ---------------------------------------------------------------------------
#define NCAND_BLK (32 * NC_MAX)

__global__ void __launch_bounds__(256) k_rescore(
    const float* __restrict__ cb, const float* __restrict__ z,
    float* __restrict__ tok_out)
{
    __shared__ float zs[32][260];
    __shared__ float zsq_s[32];
    __shared__ unsigned long long best_s[32];
    __shared__ int cnts[32], offs[33];
    __shared__ unsigned int asn[NCAND_BLK];
    const int t = threadIdx.x;
    const int n_base = blockIdx.x * 32;
    const float* zsrc = z + (size_t)(n_base >> 8) * 65536 + (n_base & 255);

    // stage z: coalesced (32 consecutive pixels per e)
    for (int idx = t; idx < 8192; idx += 256) {
        int e = idx >> 5, p = idx & 31;
        zs[p][e] = zsrc[e * 256 + p];
    }
    __syncthreads();

    if (t < 32) {
        const float* zr = zs[t];
        float s = 0.f;
        #pragma unroll 8
        for (int e = 0; e < 256; e++) { float v = zr[e]; s = fmaf(v, v, s); }
        zsq_s[t] = s;
        best_s[t] = ~0ull;
        int c = g_cnt[n_base + t];
        if (c > NC_MAX) {
            int idx = atomicAdd(&g_nfb, 1);
            g_fblist[idx] = n_base + t;
            c = 0;
        }
        cnts[t] = c;
    }
    __syncthreads();
    if (t == 0) {
        int a = 0;
        #pragma unroll
        for (int i = 0; i < 32; i++) { offs[i] = a; a += cnts[i]; }
        offs[32] = a;
    }
    __syncthreads();
    if (t < 32) {
        int o = offs[t], c = cnts[t];
        for (int i = 0; i < c; ++i)
            asn[o + i] = ((unsigned)t << 16) | g_cand[n_base + t][i];
    }
    __syncthreads();

    const int T = offs[32];
    for (int i = t; i < T; i += 256) {
        unsigned a = asn[i];
        int pl = a >> 16, v = a & 0xFFFF;
        const float* crow = cb + (size_t)v * 256;
        const float* zrow = zs[pl];
        float a0 = 0.f, a1 = 0.f, a2 = 0.f, a3 = 0.f;
        #pragma unroll 4
        for (int e = 0; e < 256; e += 16) {
            float4 z0 = *reinterpret_cast<const float4*>(zrow + e);
            float4 z1 = *reinterpret_cast<const float4*>(zrow + e + 4);
            float4 z2 = *reinterpret_cast<const float4*>(zrow + e + 8);
            float4 z3 = *reinterpret_cast<const float4*>(zrow + e + 12);
            float4 c0 = *reinterpret_cast<const float4*>(crow + e);
            float4 c1 = *reinterpret_cast<const float4*>(crow + e + 4);
            float4 c2 = *reinterpret_cast<const float4*>(crow + e + 8);
            float4 c3 = *reinterpret_cast<const float4*>(crow + e + 12);
            a0 = fmaf(z0.x, c0.x, a0); a0 = fmaf(z0.y, c0.y, a0);
            a0 = fmaf(z0.z, c0.z, a0); a0 = fmaf(z0.w, c0.w, a0);
            a1 = fmaf(z1.x, c1.x, a1); a1 = fmaf(z1.y, c1.y, a1);
            a1 = fmaf(z1.z, c1.z, a1); a1 = fmaf(z1.w, c1.w, a1);
            a2 = fmaf(z2.x, c2.x, a2); a2 = fmaf(z2.y, c2.y, a2);
            a2 = fmaf(z2.z, c2.z, a2); a2 = fmaf(z2.w, c2.w, a2);
            a3 = fmaf(z3.x, c3.x, a3); a3 = fmaf(z3.y, c3.y, a3);
            a3 = fmaf(z3.z, c3.z, a3); a3 = fmaf(z3.w, c3.w, a3);
        }
        float part = (a0 + a1) + (a2 + a3);
        float d = (zsq_s[pl] + g_csq[v]) - 2.0f * part;
        unsigned long long key = ((unsigned long long)f2ord(d) << 32) | (unsigned int)v;
        atomicMin(&best_s[pl], key);
    }
    __syncthreads();

    if (t < 32 && cnts[t] > 0) {
        int pix = n_base + t;
        int tok = (int)(best_s[t] & 0xFFFFFFFFull);
        g_tok[pix] = tok;
        tok_out[pix] = (float)tok;
    }
}

// ---------------------------------------------------------------------------
// Fallback: block-per-pixel full scan, thread-per-code.
// ---------------------------------------------------------------------------
__global__ void __launch_bounds__(256) k_fallback(
    const float* __restrict__ cb, const float* __restrict__ z,
    float* __restrict__ tok_out)
{
    __shared__ float zr[256];
    __shared__ float zsq_sh;
    __shared__ unsigned long long wmin[8];
    const int t = threadIdx.x;
    const int wid = t >> 5, lane = t & 31;
    const int n = g_nfb;

    for (int i = blockIdx.x; i < n; i += gridDim.x) {
        const int pix = g_fblist[i];
        const float* zsrc = z + (size_t)(pix >> 8) * 65536 + (pix & 255);
        zr[t] = zsrc[t * 256];
        __syncthreads();
        if (t == 0) {
            float s = 0.f;
            #pragma unroll 8
            for (int e = 0; e < 256; e++) { float v = zr[e]; s = fmaf(v, v, s); }
            zsq_sh = s;
        }
        __syncthreads();
        const float zq2 = zsq_sh;
        unsigned long long best = ~0ull;
        for (int pass = 0; pass < 16; ++pass) {
            int v = pass * 256 + t;
            const float* crow = cb + (size_t)v * 256;
            float a0 = 0.f, a1 = 0.f, a2 = 0.f, a3 = 0.f;
            #pragma unroll 8
            for (int e = 0; e < 256; e += 4) {
                a0 = fmaf(zr[e],     crow[e],     a0);
                a1 = fmaf(zr[e + 1], crow[e + 1], a1);
                a2 = fmaf(zr[e + 2], crow[e + 2], a2);
                a3 = fmaf(zr[e + 3], crow[e + 3], a3);
            }
            float part = (a0 + a1) + (a2 + a3);
            float d = (zq2 + g_csq[v]) - 2.0f * part;
            unsigned long long key = ((unsigned long long)f2ord(d) << 32) | (unsigned int)v;
            if (key < best) best = key;
        }
        #pragma unroll
        for (int o = 16; o; o >>= 1) {
            unsigned long long other = __shfl_xor_sync(0xFFFFFFFFu, best, o);
            if (other < best) best = other;
        }
        if (lane == 0) wmin[wid] = best;
        __syncthreads();
        if (t == 0) {
            unsigned long long b = wmin[0];
            #pragma unroll
            for (int k = 1; k < 8; k++) if (wmin[k] < b) b = wmin[k];
            int tok = (int)(b & 0xFFFFFFFFull);
            g_tok[pix] = tok;
            tok_out[pix] = (float)tok;
        }
        __syncthreads();
    }
}

__global__ void k_zq(const float* __restrict__ cb, float* __restrict__ zq) {
    unsigned int g = blockIdx.x * 256 + threadIdx.x;
    int hw = g & 255, e = (g >> 8) & 255, img = g >> 16;
    zq[g] = cb[(size_t)g_tok[img * 256 + hw] * 256 + e];
}

// ---------------------------------------------------------------------------
extern "C" void kernel_launch(void* const* d_in, const int* in_sizes, int n_in,
                              void* d_out, int out_size) {
    const float* x      = (const float*)d_in[0];
    const float* cb     = (const float*)d_in[1];
    const float* pre_w  = (const float*)d_in[2];
    const float* pre_b  = (const float*)d_in[3];
    const float* post_w = (const float*)d_in[4];
    const float* post_b = (const float*)d_in[5];

    float* out   = (float*)d_out;
    float* zbuf  = out;
    float* zq    = out + 8388608;
    float* recon = out + 16777216;
    float* toks  = out + 25165824;

    static bool attr_done = false;
    if (!attr_done) {
        cudaFuncSetAttribute(k_dist_mma, cudaFuncAttributeMaxDynamicSharedMemorySize, SMEM_DIST);
        attr_done = true;
    }

    k_prep<<<VOCAB, 256>>>(cb);                                        // 1
    k_gemm256<true><<<dim3(4, 4, IMGS), 256>>>(pre_w, pre_b, x, zbuf); // 2
    k_dist_mma<<<NPIX / 128, 256, SMEM_DIST>>>(zbuf);                  // 3
    k_rescore<<<NPIX / 32, 256>>>(cb, zbuf, toks);                     // 4 (profiled)
    k_fallback<<<128, 256>>>(cb, zbuf, toks);                          // 5
    k_zq<<<8388608 / 256, 256>>>(cb, zq);                              // 6
    k_gemm256<false><<<dim3(4, 4, IMGS), 256>>>(post_w, post_b, zq, recon); // 7
}

// round 9
// speedup vs baseline: 1.7015x; 1.7015x over previous
#include <cuda_runtime.h>
#include <cuda_bf16.h>
#include <cstdint>

#define IMGS   128
#define EMB    256
#define NPIX   32768
#define VOCAB  4096
#define NLRING 16          // per-(lane,row) ring capacity
#define NC_MAX 64          // max candidates per pixel (4 lanes x 16)

__device__ float g_csq[VOCAB];
__device__ float g_csqh[VOCAB];
__device__ int   g_tok[NPIX];
__device__ __nv_bfloat16 g_cbh[VOCAB * EMB];
__device__ unsigned short g_cand[NPIX][NC_MAX];
__device__ int   g_cnt[NPIX];
__device__ int   g_nfb;
__device__ int   g_fblist[NPIX];

__device__ __forceinline__ unsigned int f2ord(float f) {
    unsigned int u = __float_as_uint(f);
    return (u & 0x80000000u) ? ~u : (u | 0x80000000u);
}
__device__ __forceinline__ uint32_t smem_u32(const void* p) {
    uint32_t a;
    asm("{ .reg .u64 t; cvta.to.shared.u64 t, %1; cvt.u32.u64 %0, t; }" : "=r"(a) : "l"(p));
    return a;
}

#define LDM4(r0, r1, r2, r3, addr)                                              \
    asm volatile("ldmatrix.sync.aligned.m8n8.x4.shared.b16 {%0,%1,%2,%3}, [%4];"\
        : "=r"(r0), "=r"(r1), "=r"(r2), "=r"(r3) : "r"(addr))

#define MMA16816(d, a0, a1, a2, a3, b0, b1)                                     \
    asm volatile("mma.sync.aligned.m16n8k16.row.col.f32.bf16.bf16.f32 "         \
        "{%0,%1,%2,%3},{%4,%5,%6,%7},{%8,%9},{%0,%1,%2,%3};"                    \
        : "+f"((d)[0]), "+f"((d)[1]), "+f"((d)[2]), "+f"((d)[3])                \
        : "r"(a0), "r"(a1), "r"(a2), "r"(a3), "r"(b0), "r"(b1))

#define CPA16(dst, src)                                                         \
    asm volatile("cp.async.cg.shared.global [%0], [%1], 16;" :: "r"(dst), "l"(src))
#define CP_COMMIT() asm volatile("cp.async.commit_group;" ::: "memory")

// ---------------------------------------------------------------------------
__global__ void __launch_bounds__(256) k_prep(const float* __restrict__ cb) {
    __shared__ float red[8];
    const int r = blockIdx.x, t = threadIdx.x;
    float v = cb[r * 256 + t];
    g_cbh[r * 256 + t] = __float2bfloat16(v);
    float s = v * v;
    #pragma unroll
    for (int o = 16; o; o >>= 1) s += __shfl_down_sync(0xFFFFFFFFu, s, o);
    if ((t & 31) == 0) red[t >> 5] = s;
    __syncthreads();
    if (t == 0) {
        float tot = 0.f;
        #pragma unroll
        for (int i = 0; i < 8; i++) tot += red[i];
        g_csq[r] = tot; g_csqh[r] = 0.5f * tot;
    }
}

__global__ void k_zero() { if (threadIdx.x == 0) g_nfb = 0; }

// ---------------------------------------------------------------------------
// fp32 256x256x256 GEMM (pre/post)
// ---------------------------------------------------------------------------
template<bool XFORM>
__global__ void __launch_bounds__(256) k_gemm256(
    const float* __restrict__ W, const float* __restrict__ bias,
    const float* __restrict__ In, float* __restrict__ Out)
{
    __shared__ float Ws[16][68];
    __shared__ float Bs[16][64];
    const int img = blockIdx.z;
    const int m0 = blockIdx.y * 64, n0 = blockIdx.x * 64;
    const float* in = In + (size_t)img * 65536;
    float* out = Out + (size_t)img * 65536;
    const int t = threadIdx.x;
    const int ty = t >> 4, tx = t & 15;
    float acc[4][4] = {};
    for (int k0 = 0; k0 < 256; k0 += 16) {
        {
            int row = t >> 2, c4 = (t & 3) * 4;
            float4 w4 = *reinterpret_cast<const float4*>(&W[(m0 + row) * 256 + k0 + c4]);
            Ws[c4 + 0][row] = w4.x; Ws[c4 + 1][row] = w4.y;
            Ws[c4 + 2][row] = w4.z; Ws[c4 + 3][row] = w4.w;
        }
        {
            int kk = t >> 4, n4 = (t & 15) * 4;
            float4 b4 = *reinterpret_cast<const float4*>(&in[(k0 + kk) * 256 + n0 + n4]);
            if (XFORM) {
                b4.x = 2.f * b4.x - 1.f; b4.y = 2.f * b4.y - 1.f;
                b4.z = 2.f * b4.z - 1.f; b4.w = 2.f * b4.w - 1.f;
            }
            *reinterpret_cast<float4*>(&Bs[kk][n4]) = b4;
        }
        __syncthreads();
        #pragma unroll
        for (int kk = 0; kk < 16; kk++) {
            float a[4], b[4];
            *reinterpret_cast<float4*>(a) = *reinterpret_cast<float4*>(&Ws[kk][ty * 4]);
            *reinterpret_cast<float4*>(b) = *reinterpret_cast<float4*>(&Bs[kk][tx * 4]);
            #pragma unroll
            for (int i = 0; i < 4; i++)
                #pragma unroll
                for (int j = 0; j < 4; j++)
                    acc[i][j] += a[i] * b[j];
        }
        __syncthreads();
    }
    #pragma unroll
    for (int i = 0; i < 4; i++) {
        int m = m0 + ty * 4 + i;
        float bm = bias[m];
        float4 o;
        o.x = acc[i][0] + bm; o.y = acc[i][1] + bm;
        o.z = acc[i][2] + bm; o.w = acc[i][3] + bm;
        *reinterpret_cast<float4*>(&out[m * 256 + n0 + tx * 4]) = o;
    }
}

// ---------------------------------------------------------------------------
// bf16 mma.sync score GEMM, register-local prune into per-lane smem rings.
// SMEM: A 64KB | B0 16KB | B1 16KB | csq 256B | rings 16KB = 112.25KB
// ---------------------------------------------------------------------------
#define AOFF      0
#define B0OFF     65536
#define B1OFF     81920
#define CSQOFF    98304
#define RINGOFF   98560
#define SMEM_DIST 114944
#define MARGIN    2.5e-5f

__global__ void __launch_bounds__(256, 2) k_dist_mma(const float* __restrict__ z) {
    extern __shared__ char smem[];
    const uint32_t sb = smem_u32(smem);
    const int t = threadIdx.x;
    const int wid = t >> 5, lane = t & 31;
    const int n_base = blockIdx.x * 128;

    // ---- A build: z (fp32 [e][pix]) -> bf16 swizzled [pix][e] (scratch = B0) ----
    {
        const float* zsrc = z + (size_t)(n_base >> 8) * 65536 + (n_base & 255);
        float* scr = reinterpret_cast<float*>(smem + B0OFF);   // 32e x 128pix fp32
        for (int kb = 0; kb < 8; kb++) {
            int e_l = t >> 3;
            int pg = (t & 7) * 16;
            const float4* s4 = reinterpret_cast<const float4*>(zsrc + (kb * 32 + e_l) * 256 + pg);
            float4 v0 = s4[0], v1 = s4[1], v2 = s4[2], v3 = s4[3];
            float4* d4 = reinterpret_cast<float4*>(scr + e_l * 128 + pg);
            d4[0] = v0; d4[1] = v1; d4[2] = v2; d4[3] = v3;
            __syncthreads();
            int pix = t & 127, half = t >> 7;
            #pragma unroll
            for (int jj = 0; jj < 8; jj++) {
                int el0 = (half * 8 + jj) * 2;
                float a = scr[el0 * 128 + pix], b = scr[(el0 + 1) * 128 + pix];
                uint32_t u;
                asm("cvt.rn.bf16x2.f32 %0, %1, %2;" : "=r"(u) : "f"(b), "f"(a));
                int eg = kb * 32 + el0;
                uint32_t unit = (uint32_t)(eg >> 3);
                uint32_t su = (unit & 24) | ((unit ^ (uint32_t)(pix & 7)) & 7);
                uint32_t addr = sb + AOFF + (uint32_t)pix * 512 + su * 16 + (eg & 7) * 2;
                asm volatile("st.shared.b32 [%0], %1;" :: "r"(addr), "r"(u) : "memory");
            }
            __syncthreads();
        }
    }

    const int wbase = wid * 16;
    const int arow = wbase + (lane & 7) + ((lane >> 3) & 1) * 8;
    const uint32_t aswz = (uint32_t)(arow & 7);
    const uint32_t abase = sb + AOFF + (uint32_t)arow * 512;
    const int ag2 = lane >> 4;
    const int brp = ((lane >> 4) & 1) * 8 + (lane & 7);
    const int bg1 = (lane >> 3) & 1;
    float* csq_s = reinterpret_cast<float*>(smem + CSQOFF);
    unsigned short* ringp =
        reinterpret_cast<unsigned short*>(smem + RINGOFF) + (wid * 32 + lane) * (2 * NLRING);

    float acc[8][4];
    #pragma unroll
    for (int i = 0; i < 8; i++)
        #pragma unroll
        for (int j = 0; j < 4; j++) acc[i][j] = 0.f;

    float rmx_lo = -1e30f, rmx_hi = -1e30f;
    int cl = 0, ch = 0;

    auto loadB = [&](int nt, int kc, uint32_t boff) {
        int code = t >> 2;
        const char* src = reinterpret_cast<const char*>(
            g_cbh + ((size_t)(nt * 64 + code)) * 256 + kc * 128 + (t & 3) * 32);
        uint32_t drow = sb + boff + (uint32_t)code * 256;
        uint32_t sw = (uint32_t)(code & 7);
        #pragma unroll
        for (int i = 0; i < 4; i++) {
            uint32_t u = (uint32_t)((t & 3) * 4 + i);
            uint32_t su = ((u ^ sw) & 7) | (u & 8);
            CPA16(drow + su * 16, src + i * 16);
        }
    };

    loadB(0, 0, B0OFF);
    CP_COMMIT();

    for (int c = 0; c < 128; ++c) {
        const int nt = c >> 1, kc = c & 1;
        if (c < 127) { loadB((c + 1) >> 1, (c + 1) & 1, ((c + 1) & 1) ? B1OFF : B0OFF); CP_COMMIT(); }
        if (kc == 0 && t < 64) csq_s[t] = g_csqh[nt * 64 + t];
        if (c < 127) asm volatile("cp.async.wait_group 1;" ::: "memory");
        else         asm volatile("cp.async.wait_group 0;" ::: "memory");
        __syncthreads();

        const uint32_t bbuf = sb + ((c & 1) ? B1OFF : B0OFF);
        #pragma unroll
        for (int ks = 0; ks < 8; ks++) {
            uint32_t a0, a1, a2, a3;
            {
                uint32_t unit = (uint32_t)(kc * 16 + 2 * ks + ag2);
                uint32_t su = (unit & 24) | ((unit ^ aswz) & 7);
                LDM4(a0, a1, a2, a3, abase + su * 16);
            }
            #pragma unroll
            for (int p = 0; p < 4; p++) {
                int brow = p * 16 + brp;
                uint32_t unit = (uint32_t)(2 * ks + bg1);
                uint32_t su = (unit & 8) | ((unit ^ (uint32_t)(brow & 7)) & 7);
                uint32_t b0, b1, b2, b3;
                LDM4(b0, b1, b2, b3, bbuf + (uint32_t)brow * 256 + su * 16);
                MMA16816(acc[2 * p],     a0, a1, a2, a3, b0, b1);
                MMA16816(acc[2 * p + 1], a0, a1, a2, a3, b2, b3);
            }
        }

        if (kc == 1) {
            const int vtile = nt * 64;
            #pragma unroll
            for (int q = 0; q < 4; ++q) {
                const int cbase = q * 16 + 2 * (lane & 3);
                float2 cq0 = *reinterpret_cast<const float2*>(csq_s + cbase);
                float2 cq1 = *reinterpret_cast<const float2*>(csq_s + cbase + 8);
                const int nf0 = 2 * q, nf1 = 2 * q + 1;
                float s;
                s = acc[nf0][0] - cq0.x;
                if (s > rmx_lo - MARGIN) { if (cl < NLRING) ringp[cl] = (unsigned short)(vtile + cbase);     cl++; rmx_lo = fmaxf(rmx_lo, s); }
                s = acc[nf0][1] - cq0.y;
                if (s > rmx_lo - MARGIN) { if (cl < NLRING) ringp[cl] = (unsigned short)(vtile + cbase + 1); cl++; rmx_lo = fmaxf(rmx_lo, s); }
                s = acc[nf1][0] - cq1.x;
                if (s > rmx_lo - MARGIN) { if (cl < NLRING) ringp[cl] = (unsigned short)(vtile + cbase + 8); cl++; rmx_lo = fmaxf(rmx_lo, s); }
                s = acc[nf1][1] - cq1.y;
                if (s > rmx_lo - MARGIN) { if (cl < NLRING) ringp[cl] = (unsigned short)(vtile + cbase + 9); cl++; rmx_lo = fmaxf(rmx_lo, s); }
                s = acc[nf0][2] - cq0.x;
                if (s > rmx_hi - MARGIN) { if (ch < NLRING) ringp[NLRING + ch] = (unsigned short)(vtile + cbase);     ch++; rmx_hi = fmaxf(rmx_hi, s); }
                s = acc[nf0][3] - cq0.y;
                if (s > rmx_hi - MARGIN) { if (ch < NLRING) ringp[NLRING + ch] = (unsigned short)(vtile + cbase + 1); ch++; rmx_hi = fmaxf(rmx_hi, s); }
                s = acc[nf1][2] - cq1.x;
                if (s > rmx_hi - MARGIN) { if (ch < NLRING) ringp[NLRING + ch] = (unsigned short)(vtile + cbase + 8); ch++; rmx_hi = fmaxf(rmx_hi, s); }
                s = acc[nf1][3] - cq1.y;
                if (s > rmx_hi - MARGIN) { if (ch < NLRING) ringp[NLRING + ch] = (unsigned short)(vtile + cbase + 9); ch++; rmx_hi = fmaxf(rmx_hi, s); }
                rmx_lo = fmaxf(rmx_lo, __shfl_xor_sync(0xFFFFFFFFu, rmx_lo, 1));
                rmx_lo = fmaxf(rmx_lo, __shfl_xor_sync(0xFFFFFFFFu, rmx_lo, 2));
                rmx_hi = fmaxf(rmx_hi, __shfl_xor_sync(0xFFFFFFFFu, rmx_hi, 1));
                rmx_hi = fmaxf(rmx_hi, __shfl_xor_sync(0xFFFFFFFFu, rmx_hi, 2));
            }
            #pragma unroll
            for (int i = 0; i < 8; i++)
                #pragma unroll
                for (int j = 0; j < 4; j++) acc[i][j] = 0.f;
        }
        __syncthreads();
    }

    const unsigned qb = lane & ~3u;
    const int liq = lane & 3;
    #pragma unroll
    for (int rowsel = 0; rowsel < 2; ++rowsel) {
        int mycnt = rowsel ? ch : cl;
        int l0 = __shfl_sync(0xFFFFFFFFu, mycnt, qb + 0);
        int l1 = __shfl_sync(0xFFFFFFFFu, mycnt, qb + 1);
        int l2 = __shfl_sync(0xFFFFFFFFu, mycnt, qb + 2);
        int l3 = __shfl_sync(0xFFFFFFFFu, mycnt, qb + 3);
        int m0 = min(l0, NLRING), m1 = min(l1, NLRING),
            m2 = min(l2, NLRING), m3 = min(l3, NLRING);
        int tot = m0 + m1 + m2 + m3;
        bool ovf = (l0 > NLRING) | (l1 > NLRING) | (l2 > NLRING) | (l3 > NLRING);
        int pre = (liq > 0 ? m0 : 0) + (liq > 1 ? m1 : 0) + (liq > 2 ? m2 : 0);
        int pix = n_base + wbase + (lane >> 2) + rowsel * 8;
        if (liq == 0) g_cnt[pix] = ovf ? 1000 : tot;
        int myc = min(mycnt, NLRING);
        const unsigned short* rp = ringp + rowsel * NLRING;
        for (int i = 0; i < myc; ++i) g_cand[pix][pre + i] = rp[i];
    }
}

// ---------------------------------------------------------------------------
// Rescore: thread-per-candidate. Block = 32 pixels.
// ---------------------------------------------------------------------------
#define NCAND_BLK (32 * NC_MAX)

__global__ void __launch_bounds__(256) k_rescore(
    const float* __restrict__ cb, const float* __restrict__ z,
    float* __restrict__ tok_out)
{
    __shared__ float zs[32][260];
    __shared__ float zsq_s[32];
    __shared__ unsigned long long best_s[32];
    __shared__ int cnts[32], offs[33];
    __shared__ unsigned int asn[NCAND_BLK];
    const int t = threadIdx.x;
    const int n_base = blockIdx.x * 32;
    const float* zsrc = z + (size_t)(n_base >> 8) * 65536 + (n_base & 255);

    for (int idx = t; idx < 8192; idx += 256) {
        int e = idx >> 5, p = idx & 31;
        zs[p][e] = zsrc[e * 256 + p];
    }
    __syncthreads();

    if (t < 32) {
        const float* zr = zs[t];
        float s = 0.f;
        #pragma unroll 8
        for (int e = 0; e < 256; e++) { float v = zr[e]; s = fmaf(v, v, s); }
        zsq_s[t] = s;
        best_s[t] = ~0ull;
        int c = g_cnt[n_base + t];
        if (c > NC_MAX) {
            int idx = atomicAdd(&g_nfb, 1);
            g_fblist[idx] = n_base + t;
            c = 0;
        }
        cnts[t] = c;
    }
    __syncthreads();
    if (t == 0) {
        int a = 0;
        #pragma unroll
        for (int i = 0; i < 32; i++) { offs[i] = a; a += cnts[i]; }
        offs[32] = a;
    }
    __syncthreads();
    if (t < 32) {
        int o = offs[t], c = cnts[t];
        for (int i = 0; i < c; ++i)
            asn[o + i] = ((unsigned)t << 16) | g_cand[n_base + t][i];
    }
    __syncthreads();

    const int T = offs[32];
    for (int i = t; i < T; i += 256) {
        unsigned a = asn[i];
        int pl = a >> 16, v = a & 0xFFFF;
        const float* crow = cb + (size_t)v * 256;
        const float* zrow = zs[pl];
        float a0 = 0.f, a1 = 0.f, a2 = 0.f, a3 = 0.f;
        #pragma unroll 4
        for (int e = 0; e < 256; e += 16) {
            float4 z0 = *reinterpret_cast<const float4*>(zrow + e);
            float4 z1 = *reinterpret_cast<const float4*>(zrow + e + 4);
            float4 z2 = *reinterpret_cast<const float4*>(zrow + e + 8);
            float4 z3 = *reinterpret_cast<const float4*>(zrow + e + 12);
            float4 c0 = *reinterpret_cast<const float4*>(crow + e);
            float4 c1 = *reinterpret_cast<const float4*>(crow + e + 4);
            float4 c2 = *reinterpret_cast<const float4*>(crow + e + 8);
            float4 c3 = *reinterpret_cast<const float4*>(crow + e + 12);
            a0 = fmaf(z0.x, c0.x, a0); a0 = fmaf(z0.y, c0.y, a0);
            a0 = fmaf(z0.z, c0.z, a0); a0 = fmaf(z0.w, c0.w, a0);
            a1 = fmaf(z1.x, c1.x, a1); a1 = fmaf(z1.y, c1.y, a1);
            a1 = fmaf(z1.z, c1.z, a1); a1 = fmaf(z1.w, c1.w, a1);
            a2 = fmaf(z2.x, c2.x, a2); a2 = fmaf(z2.y, c2.y, a2);
            a2 = fmaf(z2.z, c2.z, a2); a2 = fmaf(z2.w, c2.w, a2);
            a3 = fmaf(z3.x, c3.x, a3); a3 = fmaf(z3.y, c3.y, a3);
            a3 = fmaf(z3.z, c3.z, a3); a3 = fmaf(z3.w, c3.w, a3);
        }
        float part = (a0 + a1) + (a2 + a3);
        float d = (zsq_s[pl] + g_csq[v]) - 2.0f * part;
        unsigned long long key = ((unsigned long long)f2ord(d) << 32) | (unsigned int)v;
        atomicMin(&best_s[pl], key);
    }
    __syncthreads();

    if (t < 32 && cnts[t] > 0) {
        int pix = n_base + t;
        int tok = (int)(best_s[t] & 0xFFFFFFFFull);
        g_tok[pix] = tok;
        tok_out[pix] = (float)tok;
    }
}

// ---------------------------------------------------------------------------
// Fallback v2: block-per-pixel, warp-per-code (coalesced row reads).
// ---------------------------------------------------------------------------
__global__ void __launch_bounds__(256) k_fallback(
    const float* __restrict__ cb, const float* __restrict__ z,
    float* __restrict__ tok_out)
{
    __shared__ float zr[256];
    __shared__ float zsq_sh;
    __shared__ unsigned long long wmin[8];
    const int t = threadIdx.x;
    const int wid = t >> 5, lane = t & 31;
    const int n = g_nfb;

    for (int i = blockIdx.x; i < n; i += gridDim.x) {
        const int pix = g_fblist[i];
        const float* zsrc = z + (size_t)(pix >> 8) * 65536 + (pix & 255);
        zr[t] = zsrc[t * 256];
        __syncthreads();
        if (t == 0) {
            float s = 0.f;
            #pragma unroll 8
            for (int e = 0; e < 256; e++) { float v = zr[e]; s = fmaf(v, v, s); }
            zsq_sh = s;
        }
        __syncthreads();
        const float zq2 = zsq_sh;
        const float4 z0 = *reinterpret_cast<const float4*>(zr + lane * 8);
        const float4 z1 = *reinterpret_cast<const float4*>(zr + lane * 8 + 4);
        unsigned long long best = ~0ull;

        // warp handles codes [wid*512, wid*512+512), 2 at a time
        for (int v = wid * 512; v < wid * 512 + 512; v += 2) {
            const float4* c0p = reinterpret_cast<const float4*>(cb + (size_t)v * 256 + lane * 8);
            const float4* c1p = reinterpret_cast<const float4*>(cb + (size_t)(v + 1) * 256 + lane * 8);
            float4 c00 = c0p[0], c01 = c0p[1];
            float4 c10 = c1p[0], c11 = c1p[1];
            float p0 = z0.x * c00.x, p1 = z0.x * c10.x;
            p0 = fmaf(z0.y, c00.y, p0); p1 = fmaf(z0.y, c10.y, p1);
            p0 = fmaf(z0.z, c00.z, p0); p1 = fmaf(z0.z, c10.z, p1);
            p0 = fmaf(z0.w, c00.w, p0); p1 = fmaf(z0.w, c10.w, p1);
            p0 = fmaf(z1.x, c01.x, p0); p1 = fmaf(z1.x, c11.x, p1);
            p0 = fmaf(z1.y, c01.y, p0); p1 = fmaf(z1.y, c11.y, p1);
            p0 = fmaf(z1.z, c01.z, p0); p1 = fmaf(z1.z, c11.z, p1);
            p0 = fmaf(z1.w, c01.w, p0); p1 = fmaf(z1.w, c11.w, p1);
            #pragma unroll
            for (int o = 16; o; o >>= 1) {
                p0 += __shfl_xor_sync(0xFFFFFFFFu, p0, o);
                p1 += __shfl_xor_sync(0xFFFFFFFFu, p1, o);
            }
            float d0 = (zq2 + g_csq[v])     - 2.0f * p0;
            float d1 = (zq2 + g_csq[v + 1]) - 2.0f * p1;
            unsigned long long k0 = ((unsigned long long)f2ord(d0) << 32) | (unsigned int)v;
            unsigned long long k1 = ((unsigned long long)f2ord(d1) << 32) | (unsigned int)(v + 1);
            if (k0 < best) best = k0;
            if (k1 < best) best = k1;
        }
        if (lane == 0) wmin[wid] = best;
        __syncthreads();
        if (t == 0) {
            unsigned long long b = wmin[0];
            #pragma unroll
            for (int k = 1; k < 8; k++) if (wmin[k] < b) b = wmin[k];
            int tok = (int)(b & 0xFFFFFFFFull);
            g_tok[pix] = tok;
            tok_out[pix] = (float)tok;
        }
        __syncthreads();
    }
}

__global__ void k_zq(const float* __restrict__ cb, float* __restrict__ zq) {
    unsigned int g = blockIdx.x * 256 + threadIdx.x;
    int hw = g & 255, e = (g >> 8) & 255, img = g >> 16;
    zq[g] = cb[(size_t)g_tok[img * 256 + hw] * 256 + e];
}

// ---------------------------------------------------------------------------
extern "C" void kernel_launch(void* const* d_in, const int* in_sizes, int n_in,
                              void* d_out, int out_size) {
    const float* x      = (const float*)d_in[0];
    const float* cb     = (const float*)d_in[1];
    const float* pre_w  = (const float*)d_in[2];
    const float* pre_b  = (const float*)d_in[3];
    const float* post_w = (const float*)d_in[4];
    const float* post_b = (const float*)d_in[5];

    float* out   = (float*)d_out;
    float* zbuf  = out;
    float* zq    = out + 8388608;
    float* recon = out + 16777216;
    float* toks  = out + 25165824;

    static bool attr_done = false;
    if (!attr_done) {
        cudaFuncSetAttribute(k_dist_mma, cudaFuncAttributeMaxDynamicSharedMemorySize, SMEM_DIST);
        attr_done = true;
    }

    k_prep<<<VOCAB, 256>>>(cb);                                        // 1
    k_zero<<<1, 32>>>();                                               // 2
    k_gemm256<true><<<dim3(4, 4, IMGS), 256>>>(pre_w, pre_b, x, zbuf); // 3
    k_dist_mma<<<NPIX / 128, 256, SMEM_DIST>>>(zbuf);                  // 4 (profiled slot)
    k_rescore<<<NPIX / 32, 256>>>(cb, zbuf, toks);                     // 5
    k_fallback<<<256, 256>>>(cb, zbuf, toks);                          // 6
    k_zq<<<8388608 / 256, 256>>>(cb, zq);                              // 7
    k_gemm256<false><<<dim3(4, 4, IMGS), 256>>>(post_w, post_b, zq, recon); // 8
}

// round 10
// speedup vs baseline: 1.7765x; 1.0440x over previous
#include <cuda_runtime.h>
#include <cuda_bf16.h>
#include <cstdint>

#define IMGS   128
#define EMB    256
#define NPIX   32768
#define VOCAB  4096
#define NLRING 16          // per-(lane,row) ring capacity
#define NC_MAX 64          // max candidates per pixel (4 lanes x 16)

__device__ float g_csq[VOCAB];
__device__ float g_csqh[VOCAB];
__device__ int   g_tok[NPIX];
__device__ __nv_bfloat16 g_cbh[VOCAB * EMB];
__device__ unsigned short g_cand[NPIX][NC_MAX];
__device__ int   g_cnt[NPIX];
__device__ int   g_nfb;
__device__ int   g_fblist[NPIX];

__device__ __forceinline__ unsigned int f2ord(float f) {
    unsigned int u = __float_as_uint(f);
    return (u & 0x80000000u) ? ~u : (u | 0x80000000u);
}
__device__ __forceinline__ uint32_t smem_u32(const void* p) {
    uint32_t a;
    asm("{ .reg .u64 t; cvta.to.shared.u64 t, %1; cvt.u32.u64 %0, t; }" : "=r"(a) : "l"(p));
    return a;
}

#define LDM4(r0, r1, r2, r3, addr)                                              \
    asm volatile("ldmatrix.sync.aligned.m8n8.x4.shared.b16 {%0,%1,%2,%3}, [%4];"\
        : "=r"(r0), "=r"(r1), "=r"(r2), "=r"(r3) : "r"(addr))

#define MMA16816(d, a0, a1, a2, a3, b0, b1)                                     \
    asm volatile("mma.sync.aligned.m16n8k16.row.col.f32.bf16.bf16.f32 "         \
        "{%0,%1,%2,%3},{%4,%5,%6,%7},{%8,%9},{%0,%1,%2,%3};"                    \
        : "+f"((d)[0]), "+f"((d)[1]), "+f"((d)[2]), "+f"((d)[3])                \
        : "r"(a0), "r"(a1), "r"(a2), "r"(a3), "r"(b0), "r"(b1))

#define CPA16(dst, src)                                                         \
    asm volatile("cp.async.cg.shared.global [%0], [%1], 16;" :: "r"(dst), "l"(src))
#define CP_COMMIT() asm volatile("cp.async.commit_group;" ::: "memory")

// ---------------------------------------------------------------------------
__global__ void __launch_bounds__(256) k_prep(const float* __restrict__ cb) {
    __shared__ float red[8];
    const int r = blockIdx.x, t = threadIdx.x;
    float v = cb[r * 256 + t];
    g_cbh[r * 256 + t] = __float2bfloat16(v);
    float s = v * v;
    #pragma unroll
    for (int o = 16; o; o >>= 1) s += __shfl_down_sync(0xFFFFFFFFu, s, o);
    if ((t & 31) == 0) red[t >> 5] = s;
    __syncthreads();
    if (t == 0) {
        float tot = 0.f;
        #pragma unroll
        for (int i = 0; i < 8; i++) tot += red[i];
        g_csq[r] = tot; g_csqh[r] = 0.5f * tot;
    }
}

__global__ void k_zero() { if (threadIdx.x == 0) g_nfb = 0; }

// ---------------------------------------------------------------------------
// fp32 256x256x256 GEMM (pre/post)
// ---------------------------------------------------------------------------
template<bool XFORM>
__global__ void __launch_bounds__(256) k_gemm256(
    const float* __restrict__ W, const float* __restrict__ bias,
    const float* __restrict__ In, float* __restrict__ Out)
{
    __shared__ float Ws[16][68];
    __shared__ float Bs[16][64];
    const int img = blockIdx.z;
    const int m0 = blockIdx.y * 64, n0 = blockIdx.x * 64;
    const float* in = In + (size_t)img * 65536;
    float* out = Out + (size_t)img * 65536;
    const int t = threadIdx.x;
    const int ty = t >> 4, tx = t & 15;
    float acc[4][4] = {};
    for (int k0 = 0; k0 < 256; k0 += 16) {
        {
            int row = t >> 2, c4 = (t & 3) * 4;
            float4 w4 = *reinterpret_cast<const float4*>(&W[(m0 + row) * 256 + k0 + c4]);
            Ws[c4 + 0][row] = w4.x; Ws[c4 + 1][row] = w4.y;
            Ws[c4 + 2][row] = w4.z; Ws[c4 + 3][row] = w4.w;
        }
        {
            int kk = t >> 4, n4 = (t & 15) * 4;
            float4 b4 = *reinterpret_cast<const float4*>(&in[(k0 + kk) * 256 + n0 + n4]);
            if (XFORM) {
                b4.x = 2.f * b4.x - 1.f; b4.y = 2.f * b4.y - 1.f;
                b4.z = 2.f * b4.z - 1.f; b4.w = 2.f * b4.w - 1.f;
            }
            *reinterpret_cast<float4*>(&Bs[kk][n4]) = b4;
        }
        __syncthreads();
        #pragma unroll
        for (int kk = 0; kk < 16; kk++) {
            float a[4], b[4];
            *reinterpret_cast<float4*>(a) = *reinterpret_cast<float4*>(&Ws[kk][ty * 4]);
            *reinterpret_cast<float4*>(b) = *reinterpret_cast<float4*>(&Bs[kk][tx * 4]);
            #pragma unroll
            for (int i = 0; i < 4; i++)
                #pragma unroll
                for (int j = 0; j < 4; j++)
                    acc[i][j] += a[i] * b[j];
        }
        __syncthreads();
    }
    #pragma unroll
    for (int i = 0; i < 4; i++) {
        int m = m0 + ty * 4 + i;
        float bm = bias[m];
        float4 o;
        o.x = acc[i][0] + bm; o.y = acc[i][1] + bm;
        o.z = acc[i][2] + bm; o.w = acc[i][3] + bm;
        *reinterpret_cast<float4*>(&out[m * 256 + n0 + tx * 4]) = o;
    }
}

// ---------------------------------------------------------------------------
// bf16 mma.sync score GEMM, gated register-local prune into smem rings.
// SMEM: A 64KB | B0 16KB | B1 16KB | csq 256B | rings 16KB
// ---------------------------------------------------------------------------
#define AOFF      0
#define B0OFF     65536
#define B1OFF     81920
#define CSQOFF    98304
#define RINGOFF   98560
#define SMEM_DIST 114944
#define MARGIN    2.5e-5f

__global__ void __launch_bounds__(256, 2) k_dist_mma(const float* __restrict__ z) {
    extern __shared__ char smem[];
    const uint32_t sb = smem_u32(smem);
    const int t = threadIdx.x;
    const int wid = t >> 5, lane = t & 31;
    const int n_base = blockIdx.x * 128;

    // ---- A build: z (fp32 [e][pix]) -> bf16 swizzled [pix][e] (scratch = B0) ----
    {
        const float* zsrc = z + (size_t)(n_base >> 8) * 65536 + (n_base & 255);
        float* scr = reinterpret_cast<float*>(smem + B0OFF);   // 32e x 128pix fp32
        for (int kb = 0; kb < 8; kb++) {
            int e_l = t >> 3;
            int pg = (t & 7) * 16;
            const float4* s4 = reinterpret_cast<const float4*>(zsrc + (kb * 32 + e_l) * 256 + pg);
            float4 v0 = s4[0], v1 = s4[1], v2 = s4[2], v3 = s4[3];
            float4* d4 = reinterpret_cast<float4*>(scr + e_l * 128 + pg);
            d4[0] = v0; d4[1] = v1; d4[2] = v2; d4[3] = v3;
            __syncthreads();
            int pix = t & 127, half = t >> 7;
            #pragma unroll
            for (int jj = 0; jj < 8; jj++) {
                int el0 = (half * 8 + jj) * 2;
                float a = scr[el0 * 128 + pix], b = scr[(el0 + 1) * 128 + pix];
                uint32_t u;
                asm("cvt.rn.bf16x2.f32 %0, %1, %2;" : "=r"(u) : "f"(b), "f"(a));
                int eg = kb * 32 + el0;
                uint32_t unit = (uint32_t)(eg >> 3);
                uint32_t su = (unit & 24) | ((unit ^ (uint32_t)(pix & 7)) & 7);
                uint32_t addr = sb + AOFF + (uint32_t)pix * 512 + su * 16 + (eg & 7) * 2;
                asm volatile("st.shared.b32 [%0], %1;" :: "r"(addr), "r"(u) : "memory");
            }
            __syncthreads();
        }
    }

    const int wbase = wid * 16;
    const int arow = wbase + (lane & 7) + ((lane >> 3) & 1) * 8;
    const uint32_t aswz = (uint32_t)(arow & 7);
    const uint32_t abase = sb + AOFF + (uint32_t)arow * 512;
    const int ag2 = lane >> 4;
    const int brp = ((lane >> 4) & 1) * 8 + (lane & 7);
    const int bg1 = (lane >> 3) & 1;
    float* csq_s = reinterpret_cast<float*>(smem + CSQOFF);
    unsigned short* ringp =
        reinterpret_cast<unsigned short*>(smem + RINGOFF) + (wid * 32 + lane) * (2 * NLRING);

    float acc[8][4];
    #pragma unroll
    for (int i = 0; i < 8; i++)
        #pragma unroll
        for (int j = 0; j < 4; j++) acc[i][j] = 0.f;

    float rmx_lo = -1e30f, rmx_hi = -1e30f;
    int cl = 0, ch = 0;

    auto loadB = [&](int nt, int kc, uint32_t boff) {
        int code = t >> 2;
        const char* src = reinterpret_cast<const char*>(
            g_cbh + ((size_t)(nt * 64 + code)) * 256 + kc * 128 + (t & 3) * 32);
        uint32_t drow = sb + boff + (uint32_t)code * 256;
        uint32_t sw = (uint32_t)(code & 7);
        #pragma unroll
        for (int i = 0; i < 4; i++) {
            uint32_t u = (uint32_t)((t & 3) * 4 + i);
            uint32_t su = ((u ^ sw) & 7) | (u & 8);
            CPA16(drow + su * 16, src + i * 16);
        }
    };

    loadB(0, 0, B0OFF);
    CP_COMMIT();

    for (int c = 0; c < 128; ++c) {
        const int nt = c >> 1, kc = c & 1;
        if (c < 127) { loadB((c + 1) >> 1, (c + 1) & 1, ((c + 1) & 1) ? B1OFF : B0OFF); CP_COMMIT(); }
        if (kc == 0 && t < 64) csq_s[t] = g_csqh[nt * 64 + t];
        if (c < 127) asm volatile("cp.async.wait_group 1;" ::: "memory");
        else         asm volatile("cp.async.wait_group 0;" ::: "memory");
        __syncthreads();

        const uint32_t bbuf = sb + ((c & 1) ? B1OFF : B0OFF);
        #pragma unroll
        for (int ks = 0; ks < 8; ks++) {
            uint32_t a0, a1, a2, a3;
            {
                uint32_t unit = (uint32_t)(kc * 16 + 2 * ks + ag2);
                uint32_t su = (unit & 24) | ((unit ^ aswz) & 7);
                LDM4(a0, a1, a2, a3, abase + su * 16);
            }
            #pragma unroll
            for (int p = 0; p < 4; p++) {
                int brow = p * 16 + brp;
                uint32_t unit = (uint32_t)(2 * ks + bg1);
                uint32_t su = (unit & 8) | ((unit ^ (uint32_t)(brow & 7)) & 7);
                uint32_t b0, b1, b2, b3;
                LDM4(b0, b1, b2, b3, bbuf + (uint32_t)brow * 256 + su * 16);
                MMA16816(acc[2 * p],     a0, a1, a2, a3, b0, b1);
                MMA16816(acc[2 * p + 1], a0, a1, a2, a3, b2, b3);
            }
        }

        if (kc == 1) {
            const int vtile = nt * 64;
            #pragma unroll
            for (int q = 0; q < 4; ++q) {
                const int cbase = q * 16 + 2 * (lane & 3);
                float2 cq0 = *reinterpret_cast<const float2*>(csq_s + cbase);
                float2 cq1 = *reinterpret_cast<const float2*>(csq_s + cbase + 8);
                const int nf0 = 2 * q, nf1 = 2 * q + 1;
                // low row: gate on group max (exact semantics: gate fail => no records)
                {
                    float s0 = acc[nf0][0] - cq0.x, s1 = acc[nf0][1] - cq0.y;
                    float s2 = acc[nf1][0] - cq1.x, s3 = acc[nf1][1] - cq1.y;
                    float m = fmaxf(fmaxf(s0, s1), fmaxf(s2, s3));
                    if (m > rmx_lo - MARGIN) {
                        if (s0 > rmx_lo - MARGIN) { if (cl < NLRING) ringp[cl] = (unsigned short)(vtile + cbase);     cl++; rmx_lo = fmaxf(rmx_lo, s0); }
                        if (s1 > rmx_lo - MARGIN) { if (cl < NLRING) ringp[cl] = (unsigned short)(vtile + cbase + 1); cl++; rmx_lo = fmaxf(rmx_lo, s1); }
                        if (s2 > rmx_lo - MARGIN) { if (cl < NLRING) ringp[cl] = (unsigned short)(vtile + cbase + 8); cl++; rmx_lo = fmaxf(rmx_lo, s2); }
                        if (s3 > rmx_lo - MARGIN) { if (cl < NLRING) ringp[cl] = (unsigned short)(vtile + cbase + 9); cl++; rmx_lo = fmaxf(rmx_lo, s3); }
                    }
                }
                // high row
                {
                    float s0 = acc[nf0][2] - cq0.x, s1 = acc[nf0][3] - cq0.y;
                    float s2 = acc[nf1][2] - cq1.x, s3 = acc[nf1][3] - cq1.y;
                    float m = fmaxf(fmaxf(s0, s1), fmaxf(s2, s3));
                    if (m > rmx_hi - MARGIN) {
                        if (s0 > rmx_hi - MARGIN) { if (ch < NLRING) ringp[NLRING + ch] = (unsigned short)(vtile + cbase);     ch++; rmx_hi = fmaxf(rmx_hi, s0); }
                        if (s1 > rmx_hi - MARGIN) { if (ch < NLRING) ringp[NLRING + ch] = (unsigned short)(vtile + cbase + 1); ch++; rmx_hi = fmaxf(rmx_hi, s1); }
                        if (s2 > rmx_hi - MARGIN) { if (ch < NLRING) ringp[NLRING + ch] = (unsigned short)(vtile + cbase + 8); ch++; rmx_hi = fmaxf(rmx_hi, s2); }
                        if (s3 > rmx_hi - MARGIN) { if (ch < NLRING) ringp[NLRING + ch] = (unsigned short)(vtile + cbase + 9); ch++; rmx_hi = fmaxf(rmx_hi, s3); }
                    }
                }
            }
            // quad sync of running maxima once per tile (lag is conservative-only)
            rmx_lo = fmaxf(rmx_lo, __shfl_xor_sync(0xFFFFFFFFu, rmx_lo, 1));
            rmx_lo = fmaxf(rmx_lo, __shfl_xor_sync(0xFFFFFFFFu, rmx_lo, 2));
            rmx_hi = fmaxf(rmx_hi, __shfl_xor_sync(0xFFFFFFFFu, rmx_hi, 1));
            rmx_hi = fmaxf(rmx_hi, __shfl_xor_sync(0xFFFFFFFFu, rmx_hi, 2));
            #pragma unroll
            for (int i = 0; i < 8; i++)
                #pragma unroll
                for (int j = 0; j < 4; j++) acc[i][j] = 0.f;
        }
        __syncthreads();
    }

    const unsigned qb = lane & ~3u;
    const int liq = lane & 3;
    #pragma unroll
    for (int rowsel = 0; rowsel < 2; ++rowsel) {
        int mycnt = rowsel ? ch : cl;
        int l0 = __shfl_sync(0xFFFFFFFFu, mycnt, qb + 0);
        int l1 = __shfl_sync(0xFFFFFFFFu, mycnt, qb + 1);
        int l2 = __shfl_sync(0xFFFFFFFFu, mycnt, qb + 2);
        int l3 = __shfl_sync(0xFFFFFFFFu, mycnt, qb + 3);
        int m0 = min(l0, NLRING), m1 = min(l1, NLRING),
            m2 = min(l2, NLRING), m3 = min(l3, NLRING);
        int tot = m0 + m1 + m2 + m3;
        bool ovf = (l0 > NLRING) | (l1 > NLRING) | (l2 > NLRING) | (l3 > NLRING);
        int pre = (liq > 0 ? m0 : 0) + (liq > 1 ? m1 : 0) + (liq > 2 ? m2 : 0);
        int pix = n_base + wbase + (lane >> 2) + rowsel * 8;
        if (liq == 0) g_cnt[pix] = ovf ? 1000 : tot;
        int myc = min(mycnt, NLRING);
        const unsigned short* rp = ringp + rowsel * NLRING;
        for (int i = 0; i < myc; ++i) g_cand[pix][pre + i] = rp[i];
    }
}

// ---------------------------------------------------------------------------
// Rescore v3: warp-per-candidate (coalesced cb rows), 2 in flight.
// ---------------------------------------------------------------------------
#define NCAND_BLK (32 * NC_MAX)

__global__ void __launch_bounds__(256) k_rescore(
    const float* __restrict__ cb, const float* __restrict__ z,
    float* __restrict__ tok_out)
{
    __shared__ float zs[32][260];
    __shared__ float zsq_s[32];
    __shared__ unsigned long long best_s[32];
    __shared__ int cnts[32], offs[33];
    __shared__ unsigned int asn[NCAND_BLK];
    const int t = threadIdx.x;
    const int wid = t >> 5, lane = t & 31;
    const int n_base = blockIdx.x * 32;
    const float* zsrc = z + (size_t)(n_base >> 8) * 65536 + (n_base & 255);

    for (int idx = t; idx < 8192; idx += 256) {
        int e = idx >> 5, p = idx & 31;
        zs[p][e] = zsrc[e * 256 + p];
    }
    __syncthreads();

    if (t < 32) {
        const float* zr = zs[t];
        float s = 0.f;
        #pragma unroll 8
        for (int e = 0; e < 256; e++) { float v = zr[e]; s = fmaf(v, v, s); }
        zsq_s[t] = s;
        best_s[t] = ~0ull;
        int c = g_cnt[n_base + t];
        if (c > NC_MAX) {
            int idx = atomicAdd(&g_nfb, 1);
            g_fblist[idx] = n_base + t;
            c = 0;
        }
        cnts[t] = c;
    }
    __syncthreads();
    if (t == 0) {
        int a = 0;
        #pragma unroll
        for (int i = 0; i < 32; i++) { offs[i] = a; a += cnts[i]; }
        offs[32] = a;
    }
    __syncthreads();
    if (t < 32) {
        int o = offs[t], c = cnts[t];
        for (int i = 0; i < c; ++i)
            asn[o + i] = ((unsigned)t << 16) | g_cand[n_base + t][i];
    }
    __syncthreads();

    const int T = offs[32];
    for (int i = wid; i < T; i += 16) {
        const int j = i + 8;
        unsigned a0 = asn[i];
        unsigned a1 = (j < T) ? asn[j] : a0;
        int pl0 = a0 >> 16, v0 = a0 & 0xFFFF;
        int pl1 = a1 >> 16, v1 = a1 & 0xFFFF;

        const float4* cp0 = reinterpret_cast<const float4*>(cb + (size_t)v0 * 256 + lane * 8);
        const float4* cp1 = reinterpret_cast<const float4*>(cb + (size_t)v1 * 256 + lane * 8);
        float4 c00 = cp0[0], c01 = cp0[1];
        float4 c10 = cp1[0], c11 = cp1[1];
        const float* zr0 = zs[pl0] + lane * 8;
        const float* zr1 = zs[pl1] + lane * 8;
        float4 za0 = *reinterpret_cast<const float4*>(zr0);
        float4 zb0 = *reinterpret_cast<const float4*>(zr0 + 4);
        float4 za1 = *reinterpret_cast<const float4*>(zr1);
        float4 zb1 = *reinterpret_cast<const float4*>(zr1 + 4);

        float p0 = za0.x * c00.x, p1 = za1.x * c10.x;
        p0 = fmaf(za0.y, c00.y, p0); p1 = fmaf(za1.y, c10.y, p1);
        p0 = fmaf(za0.z, c00.z, p0); p1 = fmaf(za1.z, c10.z, p1);
        p0 = fmaf(za0.w, c00.w, p0); p1 = fmaf(za1.w, c10.w, p1);
        p0 = fmaf(zb0.x, c01.x, p0); p1 = fmaf(zb1.x, c11.x, p1);
        p0 = fmaf(zb0.y, c01.y, p0); p1 = fmaf(zb1.y, c11.y, p1);
        p0 = fmaf(zb0.z, c01.z, p0); p1 = fmaf(zb1.z, c11.z, p1);
        p0 = fmaf(zb0.w, c01.w, p0); p1 = fmaf(zb1.w, c11.w, p1);
        #pragma unroll
        for (int o = 16; o; o >>= 1) {
            p0 += __shfl_xor_sync(0xFFFFFFFFu, p0, o);
            p1 += __shfl_xor_sync(0xFFFFFFFFu, p1, o);
        }
        if (lane == 0) {
            float d0 = (zsq_s[pl0] + g_csq[v0]) - 2.0f * p0;
            unsigned long long k0 = ((unsigned long long)f2ord(d0) << 32) | (unsigned int)v0;
            atomicMin(&best_s[pl0], k0);
            if (j < T) {
                float d1 = (zsq_s[pl1] + g_csq[v1]) - 2.0f * p1;
                unsigned long long k1 = ((unsigned long long)f2ord(d1) << 32) | (unsigned int)v1;
                atomicMin(&best_s[pl1], k1);
            }
        }
    }
    __syncthreads();

    if (t < 32 && cnts[t] > 0) {
        int pix = n_base + t;
        int tok = (int)(best_s[t] & 0xFFFFFFFFull);
        g_tok[pix] = tok;
        tok_out[pix] = (float)tok;
    }
}

// ---------------------------------------------------------------------------
// Fallback: block-per-pixel, warp-per-code (coalesced row reads).
// ---------------------------------------------------------------------------
__global__ void __launch_bounds__(256) k_fallback(
    const float* __restrict__ cb, const float* __restrict__ z,
    float* __restrict__ tok_out)
{
    __shared__ float zr[256];
    __shared__ float zsq_sh;
    __shared__ unsigned long long wmin[8];
    const int t = threadIdx.x;
    const int wid = t >> 5, lane = t & 31;
    const int n = g_nfb;

    for (int i = blockIdx.x; i < n; i += gridDim.x) {
        const int pix = g_fblist[i];
        const float* zsrc = z + (size_t)(pix >> 8) * 65536 + (pix & 255);
        zr[t] = zsrc[t * 256];
        __syncthreads();
        if (t == 0) {
            float s = 0.f;
            #pragma unroll 8
            for (int e = 0; e < 256; e++) { float v = zr[e]; s = fmaf(v, v, s); }
            zsq_sh = s;
        }
        __syncthreads();
        const float zq2 = zsq_sh;
        const float4 z0 = *reinterpret_cast<const float4*>(zr + lane * 8);
        const float4 z1 = *reinterpret_cast<const float4*>(zr + lane * 8 + 4);
        unsigned long long best = ~0ull;

        for (int v = wid * 512; v < wid * 512 + 512; v += 2) {
            const float4* c0p = reinterpret_cast<const float4*>(cb + (size_t)v * 256 + lane * 8);
            const float4* c1p = reinterpret_cast<const float4*>(cb + (size_t)(v + 1) * 256 + lane * 8);
            float4 c00 = c0p[0], c01 = c0p[1];
            float4 c10 = c1p[0], c11 = c1p[1];
            float p0 = z0.x * c00.x, p1 = z0.x * c10.x;
            p0 = fmaf(z0.y, c00.y, p0); p1 = fmaf(z0.y, c10.y, p1);
            p0 = fmaf(z0.z, c00.z, p0); p1 = fmaf(z0.z, c10.z, p1);
            p0 = fmaf(z0.w, c00.w, p0); p1 = fmaf(z0.w, c10.w, p1);
            p0 = fmaf(z1.x, c01.x, p0); p1 = fmaf(z1.x, c11.x, p1);
            p0 = fmaf(z1.y, c01.y, p0); p1 = fmaf(z1.y, c11.y, p1);
            p0 = fmaf(z1.z, c01.z, p0); p1 = fmaf(z1.z, c11.z, p1);
            p0 = fmaf(z1.w, c01.w, p0); p1 = fmaf(z1.w, c11.w, p1);
            #pragma unroll
            for (int o = 16; o; o >>= 1) {
                p0 += __shfl_xor_sync(0xFFFFFFFFu, p0, o);
                p1 += __shfl_xor_sync(0xFFFFFFFFu, p1, o);
            }
            float d0 = (zq2 + g_csq[v])     - 2.0f * p0;
            float d1 = (zq2 + g_csq[v + 1]) - 2.0f * p1;
            unsigned long long k0 = ((unsigned long long)f2ord(d0) << 32) | (unsigned int)v;
            unsigned long long k1 = ((unsigned long long)f2ord(d1) << 32) | (unsigned int)(v + 1);
            if (k0 < best) best = k0;
            if (k1 < best) best = k1;
        }
        if (lane == 0) wmin[wid] = best;
        __syncthreads();
        if (t == 0) {
            unsigned long long b = wmin[0];
            #pragma unroll
            for (int k = 1; k < 8; k++) if (wmin[k] < b) b = wmin[k];
            int tok = (int)(b & 0xFFFFFFFFull);
            g_tok[pix] = tok;
            tok_out[pix] = (float)tok;
        }
        __syncthreads();
    }
}

__global__ void k_zq(const float* __restrict__ cb, float* __restrict__ zq) {
    unsigned int g = blockIdx.x * 256 + threadIdx.x;
    int hw = g & 255, e = (g >> 8) & 255, img = g >> 16;
    zq[g] = cb[(size_t)g_tok[img * 256 + hw] * 256 + e];
}

// ---------------------------------------------------------------------------
extern "C" void kernel_launch(void* const* d_in, const int* in_sizes, int n_in,
                              void* d_out, int out_size) {
    const float* x      = (const float*)d_in[0];
    const float* cb     = (const float*)d_in[1];
    const float* pre_w  = (const float*)d_in[2];
    const float* pre_b  = (const float*)d_in[3];
    const float* post_w = (const float*)d_in[4];
    const float* post_b = (const float*)d_in[5];

    float* out   = (float*)d_out;
    float* zbuf  = out;
    float* zq    = out + 8388608;
    float* recon = out + 16777216;
    float* toks  = out + 25165824;

    static bool attr_done = false;
    if (!attr_done) {
        cudaFuncSetAttribute(k_dist_mma, cudaFuncAttributeMaxDynamicSharedMemorySize, SMEM_DIST);
        attr_done = true;
    }

    k_prep<<<VOCAB, 256>>>(cb);                                        // 1
    k_zero<<<1, 32>>>();                                               // 2
    k_gemm256<true><<<dim3(4, 4, IMGS), 256>>>(pre_w, pre_b, x, zbuf); // 3
    k_dist_mma<<<NPIX / 128, 256, SMEM_DIST>>>(zbuf);                  // 4 (profiled slot)
    k_rescore<<<NPIX / 32, 256>>>(cb, zbuf, toks);                     // 5
    k_fallback<<<256, 256>>>(cb, zbuf, toks);                          // 6
    k_zq<<<8388608 / 256, 256>>>(cb, zq);                              // 7
    k_gemm256<false><<<dim3(4, 4, IMGS), 256>>>(post_w, post_b, zq, recon); // 8
}